// round 11
// baseline (speedup 1.0000x reference)
#include <cuda_runtime.h>

#define NTRAJ  2048
#define TSTEPS 512
#define KDIM   (TSTEPS * 3)
#define NCH    (3 * NTRAJ)
#define NLANE  (NCH / 2)       // 3072 lanes, 2 chains each
#define PF     8
#define DT     0.00833333333333333f

// Per-(t, chain) partials (S, mah), chain = c*NTRAJ + traj. 25 MB.
__device__ float2 g_part[TSTEPS * NCH];

typedef unsigned long long u64;

__device__ __forceinline__ u64 pack2(float lo, float hi) {
    u64 v; asm("mov.b64 %0, {%1, %2};" : "=l"(v) : "f"(lo), "f"(hi)); return v;
}
__device__ __forceinline__ void unpack2(u64 v, float& lo, float& hi) {
    asm("mov.b64 {%0, %1}, %2;" : "=f"(lo), "=f"(hi) : "l"(v));
}
__device__ __forceinline__ u64 fma2(u64 a, u64 b, u64 c) {
    u64 d; asm("fma.rn.f32x2 %0, %1, %2, %3;" : "=l"(d) : "l"(a), "l"(b), "l"(c)); return d;
}
__device__ __forceinline__ u64 mul2(u64 a, u64 b) {
    u64 d; asm("mul.rn.f32x2 %0, %1, %2;" : "=l"(d) : "l"(a), "l"(b)); return d;
}
__device__ __forceinline__ u64 add2(u64 a, u64 b) {
    u64 d; asm("add.rn.f32x2 %0, %1, %2;" : "=l"(d) : "l"(a), "l"(b)); return d;
}
__device__ __forceinline__ float htanh(float x) {
    float y; asm("tanh.approx.f32 %0, %1;" : "=f"(y) : "f"(x)); return y;
}
__device__ __forceinline__ float frcp(float x) {
    float y; asm("rcp.approx.f32 %0, %1;" : "=f"(y) : "f"(x)); return y;
}

#define SGNMASK 0x8000000080000000ULL
#define NEGONE2 0xBF800000BF800000ULL   // pack(-1.f, -1.f)
#define ONE2    0x3F8000003F800000ULL   // pack( 1.f,  1.f)

// Two independent 2x2 Kalman chains per lane, packed f32x2.
// om = 1-K0 form (matches reference rounding; rel_err ~4e-7).
__device__ __forceinline__ void kstep2(
    u64& s0, u64& s1, u64& p00, u64& p01, u64& p11,
    u64 z, u64 dt2, u64 hund, u64 c1, u64 c2n, u64 c3, u64 c4,
    u64 q0, u64 q1, u64 r,
    float& Sl, float& Sh, float& Ml, float& Mh)
{
    u64 sp = fma2(dt2, s1, s0);
    u64 w  = mul2(hund, s1);
    float wl, wh; unpack2(w, wl, wh);
    u64 tv = pack2(htanh(wl), htanh(wh));
    u64 vp = fma2(c2n, tv, mul2(c1, s1));
    u64 a  = fma2(c3, mul2(tv, tv), c4);

    u64 u   = fma2(dt2, p11, p01);
    u64 n00 = add2(fma2(dt2, u, fma2(dt2, p01, p00)), q0);
    u64 n01 = mul2(a, u);
    u64 n11 = fma2(mul2(a, a), p11, q1);

    u64 S = add2(n00, r);
    unpack2(S, Sl, Sh);
    u64 is = pack2(frcp(Sl), frcp(Sh));
    u64 yv = fma2(sp, (u64)NEGONE2, z);        // z - sp (exact-equivalent)
    u64 K0 = mul2(n00, is);
    u64 K1 = mul2(n01, is);
    s0 = fma2(K0, yv, sp);
    s1 = fma2(K1, yv, vp);
    u64 om = fma2(K0, (u64)NEGONE2, (u64)ONE2); // 1 - K0
    p00 = mul2(om, n00);
    p01 = mul2(om, n01);
    p11 = fma2(K1 ^ SGNMASK, n01, n11);
    u64 mah = mul2(yv, mul2(is, yv));
    unpack2(mah, Ml, Mh);
}

// Lanes 0..2047: (x,y) blocks of trajectory L (z at 3t,3t+1: same L1 line).
// Lanes 2048..3071: theta blocks of trajectories 2p, 2p+1.
__global__ void __launch_bounds__(32, 1) ekf_k(
    const float* __restrict__ meas,
    const float* __restrict__ init_state,
    const float* __restrict__ dyna,
    const float* __restrict__ Q,
    const float* __restrict__ R,
    const float* __restrict__ P0)
{
    const int lane = threadIdx.x & 31;
    const int L    = blockIdx.x * 32 + lane;

    int cA, cB, trajA, trajB;
    if (L < NTRAJ) { cA = 0; cB = 1; trajA = L; trajB = L; }
    else { int p = L - NTRAJ; cA = 2; cB = 2; trajA = 2 * p; trajB = 2 * p + 1; }

    const int pcA = (cA == 2) ? 4 : cA,  vcA = (cA == 2) ? 5 : cA + 2;
    const int pcB = (cB == 2) ? 4 : cB,  vcB = (cB == 2) ? 5 : cB + 2;

    const float fA = (cA == 2) ? 0.0f : __ldg(dyna + 0);
    const float dA = (cA == 2) ? 0.0f : __ldg(dyna + 1);
    const float fB = (cB == 2) ? 0.0f : __ldg(dyna + 0);
    const float dB = (cB == 2) ? 0.0f : __ldg(dyna + 1);

    const u64 dt2  = pack2(DT, DT);
    const u64 hund = pack2(100.0f, 100.0f);
    const u64 c1   = pack2(1.0f - DT * dA, 1.0f - DT * dB);
    const u64 c2n  = pack2(-(DT * fA), -(DT * fB));
    const u64 c3   = pack2(100.0f * DT * fA, 100.0f * DT * fB);
    float c4l = (1.0f - DT * dA) - 100.0f * DT * fA;
    float c4h = (1.0f - DT * dB) - 100.0f * DT * fB;
    const u64 c4 = pack2(c4l, c4h);

    const u64 q0 = pack2(__ldg(Q + pcA * 7), __ldg(Q + pcB * 7));
    const u64 q1 = pack2(__ldg(Q + vcA * 7), __ldg(Q + vcB * 7));
    const u64 r  = pack2(__ldg(R + cA * 4),  __ldg(R + cB * 4));

    u64 s0 = pack2(init_state[trajA * 6 + pcA], init_state[trajB * 6 + pcB]);
    u64 s1 = pack2(init_state[trajA * 6 + vcA], init_state[trajB * 6 + vcB]);

    u64 p00 = pack2(__ldg(P0 + pcA * 7),       __ldg(P0 + pcB * 7));
    u64 p01 = pack2(__ldg(P0 + pcA * 6 + vcA), __ldg(P0 + pcB * 6 + vcB));
    u64 p11 = pack2(__ldg(P0 + vcA * 7),       __ldg(P0 + vcB * 7));

    const float* zA = meas + trajA * KDIM + cA;   // z(t) at zA[3t]
    const float* zB = meas + trajB * KDIM + cB;
    float2* ppA = g_part + (cA * NTRAJ + trajA);
    float2* ppB = g_part + (cB * NTRAJ + trajB);

    float zrA[PF], zrB[PF];
    #pragma unroll
    for (int i = 0; i < PF; ++i) { zrA[i] = zA[3 * i]; zrB[i] = zB[3 * i]; }
    const float* pzA = zA + 3 * PF;
    const float* pzB = zB + 3 * PF;

    // main loop: 504 steps with unconditional prefetch
    #pragma unroll 1
    for (int t = 0; t < TSTEPS - PF; t += PF) {
        #pragma unroll
        for (int u8 = 0; u8 < PF; ++u8) {
            u64 z = pack2(zrA[u8], zrB[u8]);
            zrA[u8] = pzA[3 * u8];
            zrB[u8] = pzB[3 * u8];
            float Sl, Sh, Ml, Mh;
            kstep2(s0, s1, p00, p01, p11, z, dt2, hund, c1, c2n, c3, c4,
                   q0, q1, r, Sl, Sh, Ml, Mh);
            ppA[u8 * NCH] = make_float2(Sl, Ml);
            ppB[u8 * NCH] = make_float2(Sh, Mh);
        }
        pzA += 3 * PF; pzB += 3 * PF;
        ppA += PF * NCH; ppB += PF * NCH;
    }
    // tail: last 8 steps
    #pragma unroll
    for (int u8 = 0; u8 < PF; ++u8) {
        u64 z = pack2(zrA[u8], zrB[u8]);
        float Sl, Sh, Ml, Mh;
        kstep2(s0, s1, p00, p01, p11, z, dt2, hund, c1, c2n, c3, c4,
               q0, q1, r, Sl, Sh, Ml, Mh);
        ppA[u8 * NCH] = make_float2(Sl, Ml);
        ppB[u8 * NCH] = make_float2(Sh, Mh);
    }
}

// loss[traj][t] = (Sx*Sy)*St + (mx+my)+mt, smem-transposed.
__global__ void combine_k(float* __restrict__ out) {
    __shared__ float tile[32][33];
    const int t0  = blockIdx.x * 32;
    const int tr0 = blockIdx.y * 32;
    const int tx = threadIdx.x, ty = threadIdx.y;

    const float2* base = g_part + (t0 + ty) * NCH + tr0 + tx;
    float2 px = base[0];
    float2 py = base[NTRAJ];
    float2 pt = base[2 * NTRAJ];
    tile[ty][tx] = fmaf(px.x * py.x, pt.x, (px.y + py.y) + pt.y);
    __syncthreads();
    out[(tr0 + ty) * TSTEPS + t0 + tx] = tile[tx][ty];
}

extern "C" void kernel_launch(void* const* d_in, const int* in_sizes, int n_in,
                              void* d_out, int out_size) {
    const float* meas = (const float*)d_in[0];
    const float* init = (const float*)d_in[1];
    const float* dyna = (const float*)d_in[2];
    const float* Q    = (const float*)d_in[3];
    const float* R    = (const float*)d_in[4];
    const float* P0   = (const float*)d_in[5];
    float* out = (float*)d_out;

    ekf_k<<<NLANE / 32, 32>>>(meas, init, dyna, Q, R, P0);
    dim3 cgrid(TSTEPS / 32, NTRAJ / 32);
    combine_k<<<cgrid, dim3(32, 32)>>>(out);
}